// round 1
// baseline (speedup 1.0000x reference)
#include <cuda_runtime.h>
#include <cuda_bf16.h>

#define N_NODES 50000
#define N_EDGES 1600000
#define DIM 128
#define NODES_PER_BLOCK 64
#define THREADS 256

// CSR row offsets scratch (allocation-free: __device__ global)
__device__ int g_row_off[N_NODES + 1];

// Kernel A: offsets[i] = lower_bound(edge_dst, i); offsets[N] = E
__global__ void build_offsets_kernel(const int* __restrict__ dst) {
    int i = blockIdx.x * blockDim.x + threadIdx.x;
    if (i > N_NODES) return;
    int lo = 0, hi = N_EDGES;
    while (lo < hi) {
        int mid = (lo + hi) >> 1;
        if (dst[mid] < i) lo = mid + 1; else hi = mid;
    }
    g_row_off[i] = lo;
}

// Kernel B: fused aggregate (warp-per-node, no atomics) + 64x128 SGEMM epilogue
__global__ __launch_bounds__(THREADS, 2)
void gcn_fused_kernel(const float* __restrict__ H,
                      const int* __restrict__ esrc,
                      const float* __restrict__ ew,
                      const float* __restrict__ W,
                      const float* __restrict__ bias,
                      float* __restrict__ out)
{
    __shared__ float sAgg[NODES_PER_BLOCK][DIM];   // 32 KB
    __shared__ float sW[DIM][DIM];                  // 64 KB
    __shared__ float sB[DIM];

    const int tid  = threadIdx.x;
    const int wid  = tid >> 5;
    const int lane = tid & 31;
    const int base = blockIdx.x * NODES_PER_BLOCK;

    // Stage W + bias into smem (coalesced float4)
    #pragma unroll
    for (int i = tid; i < DIM * DIM / 4; i += THREADS)
        ((float4*)sW)[i] = ((const float4*)W)[i];
    if (tid < DIM) sB[tid] = bias[tid];

    const float4* __restrict__ H4 = (const float4*)H;

    // -------- Aggregation: each warp handles 8 consecutive nodes --------
    #pragma unroll 1
    for (int r = 0; r < NODES_PER_BLOCK / 8; r++) {
        const int rowLocal = wid * 8 + r;
        const int node = base + rowLocal;
        float4 acc = make_float4(0.f, 0.f, 0.f, 0.f);

        if (node < N_NODES) {
            const int s = g_row_off[node];
            const int e = g_row_off[node + 1];
            for (int p = s; p < e; p += 32) {
                const int idx = p + lane;
                int   src = 0;
                float w   = 0.f;
                if (idx < e) { src = esrc[idx]; w = ew[idx]; }
                const int cnt = min(32, e - p);
                if (cnt == 32) {
                    #pragma unroll
                    for (int i = 0; i < 32; i += 4) {
                        const int   s0 = __shfl_sync(0xffffffffu, src, i);
                        const float w0 = __shfl_sync(0xffffffffu, w,   i);
                        const int   s1 = __shfl_sync(0xffffffffu, src, i + 1);
                        const float w1 = __shfl_sync(0xffffffffu, w,   i + 1);
                        const int   s2 = __shfl_sync(0xffffffffu, src, i + 2);
                        const float w2 = __shfl_sync(0xffffffffu, w,   i + 2);
                        const int   s3 = __shfl_sync(0xffffffffu, src, i + 3);
                        const float w3 = __shfl_sync(0xffffffffu, w,   i + 3);
                        const float4 h0 = H4[(size_t)s0 * 32 + lane];
                        const float4 h1 = H4[(size_t)s1 * 32 + lane];
                        const float4 h2 = H4[(size_t)s2 * 32 + lane];
                        const float4 h3 = H4[(size_t)s3 * 32 + lane];
                        acc.x += w0 * h0.x; acc.y += w0 * h0.y; acc.z += w0 * h0.z; acc.w += w0 * h0.w;
                        acc.x += w1 * h1.x; acc.y += w1 * h1.y; acc.z += w1 * h1.z; acc.w += w1 * h1.w;
                        acc.x += w2 * h2.x; acc.y += w2 * h2.y; acc.z += w2 * h2.z; acc.w += w2 * h2.w;
                        acc.x += w3 * h3.x; acc.y += w3 * h3.y; acc.z += w3 * h3.z; acc.w += w3 * h3.w;
                    }
                } else {
                    for (int i = 0; i < cnt; i++) {
                        const int   ss = __shfl_sync(0xffffffffu, src, i);
                        const float sw = __shfl_sync(0xffffffffu, w,   i);
                        const float4 h = H4[(size_t)ss * 32 + lane];
                        acc.x += sw * h.x; acc.y += sw * h.y;
                        acc.z += sw * h.z; acc.w += sw * h.w;
                    }
                }
            }
        }
        ((float4*)sAgg[rowLocal])[lane] = acc;
    }

    __syncthreads();

    // -------- GEMM epilogue: C[64x128] = sAgg[64x128] @ sW[128x128] + b --------
    // thread (ty, tx): ty = tid/32 owns rows ty*8..ty*8+7; tx = tid%32 owns cols 4tx..4tx+3
    const int tx = lane;
    const int ty = wid;
    float c[8][4];
    #pragma unroll
    for (int i = 0; i < 8; i++)
        #pragma unroll
        for (int j = 0; j < 4; j++) c[i][j] = 0.f;

    #pragma unroll 4
    for (int k = 0; k < DIM; k++) {
        const float4 bv = ((const float4*)&sW[k][0])[tx];
        #pragma unroll
        for (int i = 0; i < 8; i++) {
            const float a = sAgg[ty * 8 + i][k];   // warp-uniform broadcast
            c[i][0] += a * bv.x;
            c[i][1] += a * bv.y;
            c[i][2] += a * bv.z;
            c[i][3] += a * bv.w;
        }
    }

    const float4 bb = ((const float4*)sB)[tx];
    #pragma unroll
    for (int i = 0; i < 8; i++) {
        const int row = base + ty * 8 + i;
        if (row < N_NODES) {
            float4 o;
            o.x = c[i][0] + bb.x;
            o.y = c[i][1] + bb.y;
            o.z = c[i][2] + bb.z;
            o.w = c[i][3] + bb.w;
            ((float4*)(out + (size_t)row * DIM))[tx] = o;
        }
    }
}

extern "C" void kernel_launch(void* const* d_in, const int* in_sizes, int n_in,
                              void* d_out, int out_size) {
    const float* H    = (const float*)d_in[0];
    const int*   esrc = (const int*)  d_in[1];
    const int*   edst = (const int*)  d_in[2];
    const float* ew   = (const float*)d_in[3];
    const float* W    = (const float*)d_in[4];
    const float* b    = (const float*)d_in[5];
    float* out = (float*)d_out;

    build_offsets_kernel<<<(N_NODES + 1 + 255) / 256, 256>>>(edst);

    const int nblocks = (N_NODES + NODES_PER_BLOCK - 1) / NODES_PER_BLOCK;
    gcn_fused_kernel<<<nblocks, THREADS>>>(H, esrc, ew, W, b, out);
}